// round 3
// baseline (speedup 1.0000x reference)
#include <cuda_runtime.h>
#include <cuda_bf16.h>

#define N_NODES 100000
#define N_EDGES 800000
#define NF 81          // node features
#define NBOND 22       // bond features
#define OC 64          // out channels

// Scratch (no allocations allowed)
__device__ float  g_Q[(size_t)N_NODES * OC];   // features @ w_n[0:81]  (25.6 MB)
__device__ float4 g_xyz[N_NODES];              // packed coords (1.6 MB)
__device__ float  g_sumw[N_NODES];             // sum of 1/d^2 per src node

// ---------------------------------------------------------------------------
// K1: fused node GEMM. A = features [100k x 81], B = [w_s | w_n[0:81]] (81x128)
// out[n][c] = (A@w_s)[n][c], g_Q[n][c] = (A@w_n_node)[n][c]
// Epilogue: pack coords into g_xyz, zero g_sumw.
// ---------------------------------------------------------------------------
#define BM 128
#define ASLD 132                         // padded lead dim (16B-aligned rows, reduced conflicts)
#define K1_SMEM ((NF * ASLD + NF * 128) * 4)

__global__ __launch_bounds__(256) void k1_gemm(
    const float* __restrict__ feat,
    const float* __restrict__ w_s,
    const float* __restrict__ w_n,
    float* __restrict__ out)
{
    extern __shared__ float sm[];
    float* As = sm;                 // [NF][ASLD]  transposed A tile: As[k][r]
    float* Bs = sm + NF * ASLD;     // [NF][128]   Bs[k][c]: c<64 -> w_s, c>=64 -> w_n

    const int tid = threadIdx.x;
    const int m0  = blockIdx.x * BM;

    // Load A tile (transposed into smem), zero-fill out-of-range rows
    for (int i = tid; i < BM * NF; i += 256) {
        int r = i / NF;
        int k = i - r * NF;
        int node = m0 + r;
        As[k * ASLD + r] = (node < N_NODES) ? feat[(size_t)node * NF + k] : 0.0f;
    }
    // Load B tile: both weight halves
    for (int i = tid; i < NF * OC; i += 256) {
        int k = i >> 6;
        int c = i & 63;
        Bs[k * 128 + c]      = w_s[i];
        Bs[k * 128 + 64 + c] = w_n[i];
    }
    __syncthreads();

    // Epilogue side-outputs: coords table + sumw zeroing (one thread per row)
    if (tid < BM) {
        int node = m0 + tid;
        if (node < N_NODES) {
            g_xyz[node]  = make_float4(As[0 * ASLD + tid], As[1 * ASLD + tid],
                                       As[2 * ASLD + tid], 0.0f);
            g_sumw[node] = 0.0f;
        }
    }

    const int tx = tid & 15;   // 16 col-threads
    const int ty = tid >> 4;   // 16 row-threads

    float acc[8][8];
    #pragma unroll
    for (int i = 0; i < 8; i++)
        #pragma unroll
        for (int j = 0; j < 8; j++) acc[i][j] = 0.0f;

    const float* Ap = As + 4 * ty;
    const float* Bp = Bs + 4 * tx;

    #pragma unroll 3
    for (int k = 0; k < NF; k++) {
        float4 a0 = *(const float4*)(Ap + k * ASLD);
        float4 a1 = *(const float4*)(Ap + k * ASLD + 64);
        float4 b0 = *(const float4*)(Bp + k * 128);
        float4 b1 = *(const float4*)(Bp + k * 128 + 64);
        float av[8] = {a0.x, a0.y, a0.z, a0.w, a1.x, a1.y, a1.z, a1.w};
        float bv[8] = {b0.x, b0.y, b0.z, b0.w, b1.x, b1.y, b1.z, b1.w};
        #pragma unroll
        for (int i = 0; i < 8; i++)
            #pragma unroll
            for (int j = 0; j < 8; j++)
                acc[i][j] = fmaf(av[i], bv[j], acc[i][j]);
    }

    #pragma unroll
    for (int gi = 0; gi < 2; gi++) {
        #pragma unroll
        for (int i = 0; i < 4; i++) {
            int node = m0 + gi * 64 + 4 * ty + i;
            if (node < N_NODES) {
                int ri = gi * 4 + i;
                float4 vo = make_float4(acc[ri][0], acc[ri][1], acc[ri][2], acc[ri][3]);
                float4 vq = make_float4(acc[ri][4], acc[ri][5], acc[ri][6], acc[ri][7]);
                *(float4*)&out[(size_t)node * OC + 4 * tx] = vo;
                *(float4*)&g_Q[(size_t)node * OC + 4 * tx] = vq;
            }
        }
    }
}

// ---------------------------------------------------------------------------
// K2: warp-per-edge. contrib = invd2*Q[dst] + bond@Wb  -> red.v4 into out[src]
//     invd2 accumulated per src node into g_sumw (scalar atomic, lane 0).
// Wb (= w_n rows 81..102) held in registers: 2 columns per lane.
// ---------------------------------------------------------------------------
__global__ __launch_bounds__(256) void k2_edges(
    const float* __restrict__ bond,
    const float* __restrict__ w_n,
    const int*   __restrict__ src,
    const int*   __restrict__ dst,
    float* __restrict__ out)
{
    const int lane = threadIdx.x & 31;
    const int warp_global = (blockIdx.x * blockDim.x + threadIdx.x) >> 5;
    const int nwarps = (gridDim.x * blockDim.x) >> 5;
    const int c0 = 2 * lane;

    // Preload bond-weight columns (rows 81..102 of w_n) into registers
    float wb0[NBOND], wb1[NBOND];
    #pragma unroll
    for (int k = 0; k < NBOND; k++) {
        wb0[k] = w_n[(NF + k) * OC + c0];
        wb1[k] = w_n[(NF + k) * OC + c0 + 1];
    }

    for (int e = warp_global; e < N_EDGES; e += nwarps) {
        const int s = __ldg(&src[e]);
        const int d = __ldg(&dst[e]);

        float4 xs = __ldg(&g_xyz[s]);
        float4 xd = __ldg(&g_xyz[d]);
        float dx = xs.x - xd.x, dy = xs.y - xd.y, dz = xs.z - xd.z;
        float d2 = dx * dx + dy * dy + dz * dz;
        float w  = (d2 > 0.0f) ? (1.0f / d2) : 1e4f;   // (0.01)^-2

        float2 q = *(const float2*)&g_Q[(size_t)d * OC + c0];
        float acc0 = w * q.x;
        float acc1 = w * q.y;

        float bval = (lane < NBOND) ? __ldg(&bond[(size_t)e * NBOND + lane]) : 0.0f;
        #pragma unroll
        for (int k = 0; k < NBOND; k++) {
            float bv = __shfl_sync(0xffffffffu, bval, k);
            acc0 = fmaf(bv, wb0[k], acc0);
            acc1 = fmaf(bv, wb1[k], acc1);
        }

        // pair lanes (2l,2l+1) -> even lane holds 4 consecutive channels
        float o0 = __shfl_down_sync(0xffffffffu, acc0, 1);
        float o1 = __shfl_down_sync(0xffffffffu, acc1, 1);
        if ((lane & 1) == 0) {
            float* p = out + (size_t)s * OC + c0;   // 16B aligned (c0 % 4 == 0)
            asm volatile("red.global.add.v4.f32 [%0], {%1,%2,%3,%4};"
                         :: "l"(p), "f"(acc0), "f"(acc1), "f"(o0), "f"(o1)
                         : "memory");
        }
        if (lane == 0) atomicAdd(&g_sumw[s], w);
    }
}

// ---------------------------------------------------------------------------
// K3: out[n][c] += (Q[n][c] - C[n][c]) * sumw[n],
//     C[n][c] = sum_{k<3} feat[n][k] * w_n[k][c]
// One thread per 4 channels (float4).
// ---------------------------------------------------------------------------
__global__ __launch_bounds__(256) void k3_final(
    const float* __restrict__ feat,
    const float* __restrict__ w_n,
    float* __restrict__ out)
{
    int idx = blockIdx.x * blockDim.x + threadIdx.x;
    if (idx >= N_NODES * (OC / 4)) return;
    int n = idx >> 4;           // OC/4 == 16 groups per node
    int c = (idx & 15) * 4;

    float sw = g_sumw[n];
    if (sw == 0.0f) return;     // no edges from this node

    float f0 = __ldg(&feat[(size_t)n * NF + 0]);
    float f1 = __ldg(&feat[(size_t)n * NF + 1]);
    float f2 = __ldg(&feat[(size_t)n * NF + 2]);

    float4 q = *(const float4*)&g_Q[(size_t)n * OC + c];
    float4 o = *(const float4*)&out[(size_t)n * OC + c];

    #pragma unroll
    for (int j = 0; j < 4; j++) {
        float cv = f0 * __ldg(&w_n[0 * OC + c + j])
                 + f1 * __ldg(&w_n[1 * OC + c + j])
                 + f2 * __ldg(&w_n[2 * OC + c + j]);
        float qv = (j == 0) ? q.x : (j == 1) ? q.y : (j == 2) ? q.z : q.w;
        float ov = (j == 0) ? o.x : (j == 1) ? o.y : (j == 2) ? o.z : o.w;
        ov = fmaf(qv - cv, sw, ov);
        if (j == 0) o.x = ov; else if (j == 1) o.y = ov; else if (j == 2) o.z = ov; else o.w = ov;
    }
    *(float4*)&out[(size_t)n * OC + c] = o;
}

// ---------------------------------------------------------------------------
extern "C" void kernel_launch(void* const* d_in, const int* in_sizes, int n_in,
                              void* d_out, int out_size)
{
    const float* feat = (const float*)d_in[0];
    const float* bond = (const float*)d_in[1];
    const float* w_s  = (const float*)d_in[2];
    const float* w_n  = (const float*)d_in[3];
    const int*   src  = (const int*)  d_in[4];
    const int*   dst  = (const int*)  d_in[5];
    float* out = (float*)d_out;

    // Idempotent; if it errors during capture the attribute was already set
    // on the correctness call (process-persistent).
    (void)cudaFuncSetAttribute(k1_gemm, cudaFuncAttributeMaxDynamicSharedMemorySize, K1_SMEM);

    int grid1 = (N_NODES + BM - 1) / BM;                 // 782
    k1_gemm<<<grid1, 256, K1_SMEM>>>(feat, w_s, w_n, out);

    k2_edges<<<1184, 256>>>(bond, w_n, src, dst, out);   // ~85 edges per warp

    int grid3 = (N_NODES * (OC / 4) + 255) / 256;        // 6250
    k3_final<<<grid3, 256>>>(feat, w_n, out);
}

// round 5
// speedup vs baseline: 1.4035x; 1.4035x over previous
#include <cuda_runtime.h>
#include <cuda_bf16.h>

#define N_NODES 100000
#define N_EDGES 800000
#define NF 81          // node features
#define NBOND 22       // bond features
#define OC 64          // out channels

typedef unsigned long long ull;

// Scratch (no allocations allowed)
__device__ float  g_Q[(size_t)N_NODES * OC];   // features @ w_n[0:81]  (25.6 MB)
__device__ float4 g_xyz[N_NODES];              // packed coords (1.6 MB)
__device__ float  g_sumw[N_NODES];             // sum of 1/d^2 per src node

// ---- packed fp32x2 helpers (Blackwell FFMA2) --------------------------------
__device__ __forceinline__ void ffma2(ull& d, ull a, ull b) {
    asm("fma.rn.f32x2 %0, %1, %2, %0;" : "+l"(d) : "l"(a), "l"(b));
}
__device__ __forceinline__ ull pack2(float x) {
    ull r; asm("mov.b64 %0, {%1, %1};" : "=l"(r) : "f"(x)); return r;
}
__device__ __forceinline__ ull pack2f(float x, float y) {
    ull r; asm("mov.b64 %0, {%1, %2};" : "=l"(r) : "f"(x), "f"(y)); return r;
}
__device__ __forceinline__ float2 unpack2(ull v) {
    float2 r; asm("mov.b64 {%0, %1}, %2;" : "=f"(r.x), "=f"(r.y) : "l"(v)); return r;
}

// ---------------------------------------------------------------------------
// K1: fused node GEMM with packed f32x2 FFMA.
// A = features [100k x 81], B = [w_s | w_n[0:81]] (81x128)
// out[n][c] = (A@w_s)[n][c], g_Q[n][c] = (A@w_n_node)[n][c]
// Epilogue: pack coords into g_xyz, zero g_sumw.
// ---------------------------------------------------------------------------
#define BM 128
#define ASLD 132
#define K1_SMEM ((NF * ASLD + NF * 128) * 4)

__global__ __launch_bounds__(256) void k1_gemm(
    const float* __restrict__ feat,
    const float* __restrict__ w_s,
    const float* __restrict__ w_n,
    float* __restrict__ out)
{
    extern __shared__ float sm[];
    float* As = sm;                 // [NF][ASLD]  transposed A tile: As[k][r]
    float* Bs = sm + NF * ASLD;     // [NF][128]   Bs[k][c]: c<64 -> w_s, c>=64 -> w_n

    const int tid = threadIdx.x;
    const int m0  = blockIdx.x * BM;

    for (int i = tid; i < BM * NF; i += 256) {
        int r = i / NF;
        int k = i - r * NF;
        int node = m0 + r;
        As[k * ASLD + r] = (node < N_NODES) ? feat[(size_t)node * NF + k] : 0.0f;
    }
    for (int i = tid; i < NF * OC; i += 256) {
        int k = i >> 6;
        int c = i & 63;
        Bs[k * 128 + c]      = w_s[i];
        Bs[k * 128 + 64 + c] = w_n[i];
    }
    __syncthreads();

    if (tid < BM) {
        int node = m0 + tid;
        if (node < N_NODES) {
            g_xyz[node]  = make_float4(As[0 * ASLD + tid], As[1 * ASLD + tid],
                                       As[2 * ASLD + tid], 0.0f);
            g_sumw[node] = 0.0f;
        }
    }

    const int tx = tid & 15;   // 16 col-threads (4 cols each, in column PAIRS)
    const int ty = tid >> 4;   // 16 row-threads (8 rows each)

    ull acc[8][4];
    #pragma unroll
    for (int i = 0; i < 8; i++)
        #pragma unroll
        for (int j = 0; j < 4; j++) acc[i][j] = 0ULL;

    const float* Ap = As + 4 * ty;
    const float* Bp = Bs + 4 * tx;

    #pragma unroll 3
    for (int k = 0; k < NF; k++) {
        float4 a0 = *(const float4*)(Ap + k * ASLD);
        float4 a1 = *(const float4*)(Ap + k * ASLD + 64);
        ulonglong2 b01 = *(const ulonglong2*)(Bp + k * 128);        // cols 4tx..4tx+3 (w_s half)
        ulonglong2 b23 = *(const ulonglong2*)(Bp + k * 128 + 64);   // cols 64+4tx..  (w_n half)
        ull av[8];
        av[0] = pack2(a0.x); av[1] = pack2(a0.y); av[2] = pack2(a0.z); av[3] = pack2(a0.w);
        av[4] = pack2(a1.x); av[5] = pack2(a1.y); av[6] = pack2(a1.z); av[7] = pack2(a1.w);
        #pragma unroll
        for (int i = 0; i < 8; i++) {
            ffma2(acc[i][0], av[i], b01.x);
            ffma2(acc[i][1], av[i], b01.y);
            ffma2(acc[i][2], av[i], b23.x);
            ffma2(acc[i][3], av[i], b23.y);
        }
    }

    #pragma unroll
    for (int gi = 0; gi < 2; gi++) {
        #pragma unroll
        for (int i = 0; i < 4; i++) {
            int node = m0 + gi * 64 + 4 * ty + i;
            if (node < N_NODES) {
                int ri = gi * 4 + i;
                float2 p0 = unpack2(acc[ri][0]);
                float2 p1 = unpack2(acc[ri][1]);
                float2 p2 = unpack2(acc[ri][2]);
                float2 p3 = unpack2(acc[ri][3]);
                *(float4*)&out[(size_t)node * OC + 4 * tx] = make_float4(p0.x, p0.y, p1.x, p1.y);
                *(float4*)&g_Q[(size_t)node * OC + 4 * tx] = make_float4(p2.x, p2.y, p3.x, p3.y);
            }
        }
    }
}

// ---------------------------------------------------------------------------
// K2: block-per-256-edge tile.
//  Phase A: per-thread edge preprocessing (coalesced idx loads, xyz gather,
//           w = 1/d^2, sumw atomic) + bond staged to smem DUPLICATED (v,v)
//           so the inner loop consumes it directly as f32x2.
//  Phase B: warp iterates its 32 edges; per edge:
//           gather Q[dst] (issued early), 22x (LDS.64 broadcast + FFMA2),
//           pair-combine, red.global.add.v4 into out[src].
// ---------------------------------------------------------------------------
#define TE 256
#define K2_SMEM (TE * NBOND * 8 + TE * 12)   // 45056 + 3072 = 48128 B

__global__ __launch_bounds__(256) void k2_edges(
    const float* __restrict__ bond,
    const float* __restrict__ w_n,
    const int*   __restrict__ src,
    const int*   __restrict__ dst,
    float* __restrict__ out)
{
    extern __shared__ char smraw[];
    ull*   bd  = (ull*)smraw;                 // [TE][NBOND] duplicated bond
    int*   s_s = (int*)(bd + TE * NBOND);     // [TE]
    int*   s_d = s_s + TE;                    // [TE]
    float* s_w = (float*)(s_d + TE);          // [TE]

    const int tid  = threadIdx.x;
    const int base = blockIdx.x * TE;         // N_EDGES = 3125 * 256 exactly

    // Phase A1: per-edge scalars
    {
        int e = base + tid;
        int s = __ldg(&src[e]);
        int d = __ldg(&dst[e]);
        float4 xs = __ldg(&g_xyz[s]);
        float4 xd = __ldg(&g_xyz[d]);
        float dx = xs.x - xd.x, dy = xs.y - xd.y, dz = xs.z - xd.z;
        float d2 = dx * dx + dy * dy + dz * dz;
        float w  = (d2 > 0.0f) ? (1.0f / d2) : 1e4f;
        s_s[tid] = s; s_d[tid] = d; s_w[tid] = w;
        atomicAdd(&g_sumw[s], w);
    }
    // Phase A2: stage bond, duplicated into f32x2 pairs (coalesced global reads)
    {
        const float* bsrc = bond + (size_t)base * NBOND;
        #pragma unroll
        for (int i = tid; i < TE * NBOND; i += 256) {
            float v = __ldg(&bsrc[i]);
            bd[i] = pack2(v);
        }
    }
    __syncthreads();

    const int warp = tid >> 5;
    const int lane = tid & 31;
    const int c0   = 2 * lane;

    // bond-weight column pair for this lane, as packed f32x2 (contiguous floats)
    ull wb[NBOND];
    #pragma unroll
    for (int k = 0; k < NBOND; k++)
        wb[k] = *(const ull*)&w_n[(NF + k) * OC + c0];

    #pragma unroll 2
    for (int j = 0; j < 32; j++) {
        const int el = warp * 32 + j;
        const int d  = s_d[el];
        const int s  = s_s[el];
        const float w = s_w[el];

        // issue Q gather early; its latency hides under the 22 FFMA2 below
        float2 q = *(const float2*)&g_Q[(size_t)d * OC + c0];

        ull acc = 0ULL;
        const ull* bp = bd + el * NBOND;
        #pragma unroll
        for (int k = 0; k < NBOND; k++)
            ffma2(acc, bp[k], wb[k]);

        // acc += w * q
        ffma2(acc, pack2(w), pack2f(q.x, q.y));

        float2 a = unpack2(acc);
        float o0 = __shfl_down_sync(0xffffffffu, a.x, 1);
        float o1 = __shfl_down_sync(0xffffffffu, a.y, 1);
        if ((lane & 1) == 0) {
            float* p = out + (size_t)s * OC + c0;   // 16B aligned
            asm volatile("red.global.add.v4.f32 [%0], {%1,%2,%3,%4};"
                         :: "l"(p), "f"(a.x), "f"(a.y), "f"(o0), "f"(o1)
                         : "memory");
        }
    }
}

// ---------------------------------------------------------------------------
// K3: out[n][c] += (Q[n][c] - C[n][c]) * sumw[n],
//     C[n][c] = sum_{k<3} feat[n][k] * w_n[k][c]     (w_n top rows in smem)
// Block = 64 nodes x 4 threads; 16 channels per thread.
// ---------------------------------------------------------------------------
__global__ __launch_bounds__(256) void k3_final(
    const float* __restrict__ feat,
    const float* __restrict__ w_n,
    float* __restrict__ out)
{
    __shared__ float w3[3 * OC];
    const int tid = threadIdx.x;
    if (tid < 3 * OC) w3[tid] = w_n[tid];
    __syncthreads();

    const int n  = blockIdx.x * 64 + (tid >> 2);
    const int c0 = (tid & 3) * 16;
    if (n >= N_NODES) return;

    float sw = g_sumw[n];
    if (sw == 0.0f) return;

    float f0 = __ldg(&feat[(size_t)n * NF + 0]);
    float f1 = __ldg(&feat[(size_t)n * NF + 1]);
    float f2 = __ldg(&feat[(size_t)n * NF + 2]);

    #pragma unroll
    for (int g = 0; g < 4; g++) {
        int c = c0 + g * 4;
        float4 q = *(const float4*)&g_Q[(size_t)n * OC + c];
        float4 o = *(const float4*)&out[(size_t)n * OC + c];
        float4 cw0 = *(const float4*)&w3[0 * OC + c];
        float4 cw1 = *(const float4*)&w3[1 * OC + c];
        float4 cw2 = *(const float4*)&w3[2 * OC + c];
        o.x = fmaf(q.x - (f0 * cw0.x + f1 * cw1.x + f2 * cw2.x), sw, o.x);
        o.y = fmaf(q.y - (f0 * cw0.y + f1 * cw1.y + f2 * cw2.y), sw, o.y);
        o.z = fmaf(q.z - (f0 * cw0.z + f1 * cw1.z + f2 * cw2.z), sw, o.z);
        o.w = fmaf(q.w - (f0 * cw0.w + f1 * cw1.w + f2 * cw2.w), sw, o.w);
        *(float4*)&out[(size_t)n * OC + c] = o;
    }
}

// ---------------------------------------------------------------------------
extern "C" void kernel_launch(void* const* d_in, const int* in_sizes, int n_in,
                              void* d_out, int out_size)
{
    const float* feat = (const float*)d_in[0];
    const float* bond = (const float*)d_in[1];
    const float* w_s  = (const float*)d_in[2];
    const float* w_n  = (const float*)d_in[3];
    const int*   src  = (const int*)  d_in[4];
    const int*   dst  = (const int*)  d_in[5];
    float* out = (float*)d_out;

    (void)cudaFuncSetAttribute(k1_gemm, cudaFuncAttributeMaxDynamicSharedMemorySize, K1_SMEM);

    int grid1 = (N_NODES + BM - 1) / BM;                 // 782
    k1_gemm<<<grid1, 256, K1_SMEM>>>(feat, w_s, w_n, out);

    k2_edges<<<N_EDGES / TE, 256, K2_SMEM>>>(bond, w_n, src, dst, out);   // 3125 blocks

    int grid3 = (N_NODES + 63) / 64;                     // 1563
    k3_final<<<grid3, 256>>>(feat, w_n, out);
}